// round 1
// baseline (speedup 1.0000x reference)
#include <cuda_runtime.h>
#include <cuda_bf16.h>
#include <cstdint>

#define NROWS 20736
#define DIMX 1024
#define HIDX 4096
#define KIN  3072

// ------------------------- scratch (device globals; no allocs) -------------------------
__device__ __align__(16) __nv_bfloat16 g_A0h[(size_t)NROWS * KIN];
__device__ __align__(16) __nv_bfloat16 g_A0l[(size_t)NROWS * KIN];
__device__ __align__(16) __nv_bfloat16 g_hh[(size_t)NROWS * DIMX];
__device__ __align__(16) __nv_bfloat16 g_hl[(size_t)NROWS * DIMX];
__device__ __align__(16) __nv_bfloat16 g_uh[(size_t)NROWS * HIDX];
__device__ __align__(16) __nv_bfloat16 g_ul[(size_t)NROWS * HIDX];
__device__ __align__(16) float         g_h [(size_t)NROWS * DIMX];

__device__ __align__(16) __nv_bfloat16 g_wq_in[DIMX * KIN];
__device__ __align__(16) __nv_bfloat16 g_wq1[2 * HIDX * DIMX];
__device__ __align__(16) __nv_bfloat16 g_wq2[2 * DIMX * HIDX];
__device__ __align__(16) __nv_bfloat16 g_wqz[DIMX * DIMX];
__device__ __align__(16) __nv_bfloat16 g_wqm[DIMX];

#define NPART 512
__device__ double g_part[8][NPART];
__device__ float  g_scale[8];

// ------------------------- quantization: a = mean|W| + 1e-8 -------------------------
__global__ void k_abssum(const float* __restrict__ w, long n, int idx) {
    double s = 0.0;
    for (long i = (long)blockIdx.x * blockDim.x + threadIdx.x; i < n;
         i += (long)gridDim.x * blockDim.x)
        s += fabs((double)w[i]);
    __shared__ double sh[256];
    sh[threadIdx.x] = s;
    __syncthreads();
    for (int o = 128; o > 0; o >>= 1) {
        if (threadIdx.x < o) sh[threadIdx.x] += sh[threadIdx.x + o];
        __syncthreads();
    }
    if (threadIdx.x == 0) g_part[idx][blockIdx.x] = sh[0];  // fixed slot => deterministic
}

__global__ void k_finalize() {
    int i = threadIdx.x;  // one thread per tensor, sequential fixed-order sum
    if (i >= 7) return;
    const double cnt[7] = {3145728.0, 4194304.0, 4194304.0, 4194304.0,
                           4194304.0, 1048576.0, 1024.0};
    double s = 0.0;
    for (int j = 0; j < NPART; j++) s += g_part[i][j];
    g_scale[i] = (float)(s / cnt[i]) + 1e-8f;
}

__global__ void k_quant(const float* __restrict__ w, __nv_bfloat16* __restrict__ q,
                        long n, int sidx) {
    float a = g_scale[sidx];
    for (long i = (long)blockIdx.x * blockDim.x + threadIdx.x; i < n;
         i += (long)gridDim.x * blockDim.x) {
        float t = rintf(w[i] / a);                 // round-half-even, matches jnp.round
        t = fminf(1.0f, fmaxf(-1.0f, t));
        q[i] = __float2bfloat16(t);                // exact: {-1,0,1}
    }
}

// ------------------------- concat + hi/lo split of inputs -------------------------
__global__ void k_build_a0(const float* __restrict__ x, const float* __restrict__ y,
                           const float* __restrict__ s) {
    size_t n = (size_t)NROWS * KIN;
    for (size_t i = (size_t)blockIdx.x * blockDim.x + threadIdx.x; i < n;
         i += (size_t)gridDim.x * blockDim.x) {
        size_t row = i / KIN;
        int c = (int)(i % KIN);
        float v = (c < DIMX)     ? x[row * DIMX + c]
                : (c < 2 * DIMX) ? y[row * DIMX + (c - DIMX)]
                                 : s[row * DIMX + (c - 2 * DIMX)];
        __nv_bfloat16 hi = __float2bfloat16(v);
        g_A0h[i] = hi;
        g_A0l[i] = __float2bfloat16(v - __bfloat162float(hi));  // residual exact in fp32
    }
}

// ------------------------- GEMM: 128x128x32 bf16 mma.sync, hi/lo double-pass -------------------------
__device__ __forceinline__ void cpasync16(void* smem, const void* gmem) {
    unsigned s = (unsigned)__cvta_generic_to_shared(smem);
    asm volatile("cp.async.cg.shared.global [%0], [%1], 16;\n" ::"r"(s), "l"(gmem));
}
__device__ __forceinline__ void cp_commit() { asm volatile("cp.async.commit_group;\n"); }
__device__ __forceinline__ void cp_wait1()  { asm volatile("cp.async.wait_group 1;\n"); }

__device__ __forceinline__ float gelu_f(float x) {
    return 0.5f * x * (1.0f + erff(x * 0.70710678118654752f));
}

enum { EPI_H = 0, EPI_GELU = 1, EPI_RES = 2, EPI_Z = 3 };

template <int EPI>
__global__ void __launch_bounds__(256, 2)
k_gemm(const __nv_bfloat16* __restrict__ Ah, const __nv_bfloat16* __restrict__ Al,
       const __nv_bfloat16* __restrict__ Bw, int K,
       const float* __restrict__ bias, int sidx, int Ncols,
       float* __restrict__ Hio,
       __nv_bfloat16* __restrict__ Oh, __nv_bfloat16* __restrict__ Ol,
       float* __restrict__ Zout) {
    __shared__ __align__(16) __nv_bfloat16 sA[2][128][40];
    __shared__ __align__(16) __nv_bfloat16 sB[2][128][40];
    const int tid = threadIdx.x, lane = tid & 31, wid = tid >> 5;
    const int bm = blockIdx.y * 128, bn = blockIdx.x * 128;
    const int wm = (wid >> 2) * 64, wn = (wid & 3) * 32;

    float acc[4][4][4];
#pragma unroll
    for (int i = 0; i < 4; i++)
#pragma unroll
        for (int j = 0; j < 4; j++)
#pragma unroll
            for (int k = 0; k < 4; k++) acc[i][j][k] = 0.0f;

    const int KT = (2 * K) / 32;  // hi pass then lo pass

#define LOAD_TILE(kt, buf)                                                          \
    do {                                                                            \
        int kk = (kt) * 32;                                                         \
        const __nv_bfloat16* As = (kk < K) ? Ah : Al;                               \
        int k0 = (kk < K) ? kk : (kk - K);                                          \
        _Pragma("unroll") for (int i = 0; i < 2; i++) {                             \
            int j = tid + i * 256;                                                  \
            int r = j >> 2, c = j & 3;                                              \
            cpasync16(&sA[buf][r][c * 8], As + (size_t)(bm + r) * K + k0 + c * 8);  \
            cpasync16(&sB[buf][r][c * 8], Bw + (size_t)(bn + r) * K + k0 + c * 8);  \
        }                                                                           \
    } while (0)

    LOAD_TILE(0, 0);
    cp_commit();

    for (int kt = 0; kt < KT; kt++) {
        int buf = kt & 1;
        if (kt + 1 < KT) LOAD_TILE(kt + 1, buf ^ 1);
        cp_commit();
        cp_wait1();
        __syncthreads();
#pragma unroll
        for (int ks = 0; ks < 2; ks++) {
            uint32_t af[4][4], bf[4][2];
#pragma unroll
            for (int mf = 0; mf < 4; mf++) {
                const __nv_bfloat16* p =
                    &sA[buf][wm + mf * 16 + (lane & 15)][ks * 16 + (lane >> 4) * 8];
                unsigned s = (unsigned)__cvta_generic_to_shared(p);
                asm volatile(
                    "ldmatrix.sync.aligned.m8n8.x4.shared.b16 {%0,%1,%2,%3}, [%4];"
                    : "=r"(af[mf][0]), "=r"(af[mf][1]), "=r"(af[mf][2]), "=r"(af[mf][3])
                    : "r"(s));
            }
#pragma unroll
            for (int nh = 0; nh < 2; nh++) {
                const __nv_bfloat16* p =
                    &sB[buf][wn + nh * 16 + (lane & 15)][ks * 16 + (lane >> 4) * 8];
                unsigned s = (unsigned)__cvta_generic_to_shared(p);
                uint32_t r0, r1, r2, r3;
                asm volatile(
                    "ldmatrix.sync.aligned.m8n8.x4.shared.b16 {%0,%1,%2,%3}, [%4];"
                    : "=r"(r0), "=r"(r1), "=r"(r2), "=r"(r3)
                    : "r"(s));
                bf[nh * 2 + 0][0] = r0; bf[nh * 2 + 0][1] = r2;
                bf[nh * 2 + 1][0] = r1; bf[nh * 2 + 1][1] = r3;
            }
#pragma unroll
            for (int mf = 0; mf < 4; mf++)
#pragma unroll
                for (int nf = 0; nf < 4; nf++)
                    asm volatile(
                        "mma.sync.aligned.m16n8k16.row.col.f32.bf16.bf16.f32 "
                        "{%0,%1,%2,%3},{%4,%5,%6,%7},{%8,%9},{%0,%1,%2,%3};"
                        : "+f"(acc[mf][nf][0]), "+f"(acc[mf][nf][1]),
                          "+f"(acc[mf][nf][2]), "+f"(acc[mf][nf][3])
                        : "r"(af[mf][0]), "r"(af[mf][1]), "r"(af[mf][2]), "r"(af[mf][3]),
                          "r"(bf[nf][0]), "r"(bf[nf][1]));
        }
        __syncthreads();
    }

    const float a_s = g_scale[sidx];
#pragma unroll
    for (int mf = 0; mf < 4; mf++) {
#pragma unroll
        for (int nf = 0; nf < 4; nf++) {
            int col = bn + wn + nf * 8 + (lane & 3) * 2;
            float b0 = bias[col], b1 = bias[col + 1];
#pragma unroll
            for (int h2 = 0; h2 < 2; h2++) {
                int row = bm + wm + mf * 16 + (lane >> 2) + h2 * 8;
                size_t o = (size_t)row * Ncols + col;
                float v0 = fmaf(a_s, acc[mf][nf][h2 * 2 + 0], b0);
                float v1 = fmaf(a_s, acc[mf][nf][h2 * 2 + 1], b1);
                if (EPI == EPI_RES) {
                    float2 hp = *(const float2*)&Hio[o];
                    v0 += hp.x; v1 += hp.y;
                }
                if (EPI == EPI_GELU) { v0 = gelu_f(v0); v1 = gelu_f(v1); }
                if (EPI == EPI_H || EPI == EPI_RES) {
                    float2 w; w.x = v0; w.y = v1;
                    *(float2*)&Hio[o] = w;
                }
                if (EPI == EPI_Z) {
                    float2 w; w.x = v0; w.y = v1;
                    *(float2*)&Zout[o] = w;
                }
                if (EPI != EPI_Z) {
                    __nv_bfloat16 h0 = __float2bfloat16(v0);
                    __nv_bfloat16 h1 = __float2bfloat16(v1);
                    __nv_bfloat162 ph; ph.x = h0; ph.y = h1;
                    *(__nv_bfloat162*)&Oh[o] = ph;
                    __nv_bfloat162 pl;
                    pl.x = __float2bfloat16(v0 - __bfloat162float(h0));
                    pl.y = __float2bfloat16(v1 - __bfloat162float(h1));
                    *(__nv_bfloat162*)&Ol[o] = pl;
                }
            }
        }
    }
#undef LOAD_TILE
}

// ------------------------- focus mask: one warp per row -------------------------
__global__ void k_focus(const float* __restrict__ h, const float* __restrict__ bm,
                        float* __restrict__ out) {
    int row = blockIdx.x * 8 + (threadIdx.x >> 5);
    int lane = threadIdx.x & 31;
    if (row >= NROWS) return;
    const float* hr = h + (size_t)row * DIMX;
    float sum = 0.0f;
    for (int c = lane; c < DIMX; c += 32) sum += hr[c] * __bfloat162float(g_wqm[c]);
#pragma unroll
    for (int o = 16; o; o >>= 1) sum += __shfl_xor_sync(0xffffffffu, sum, o);
    if (lane == 0) {
        float v = g_scale[6] * sum + bm[0];
        out[row] = 1.0f / (1.0f + expf(-v));
    }
}

// ------------------------- launcher -------------------------
extern "C" void kernel_launch(void* const* d_in, const int* in_sizes, int n_in,
                              void* d_out, int out_size) {
    const float* x    = (const float*)d_in[0];
    const float* y    = (const float*)d_in[1];
    const float* sp   = (const float*)d_in[2];
    const float* W_in = (const float*)d_in[3];
    const float* b_in = (const float*)d_in[4];
    const float* W1   = (const float*)d_in[5];
    const float* b1   = (const float*)d_in[6];
    const float* W2   = (const float*)d_in[7];
    const float* b2   = (const float*)d_in[8];
    const float* W_z  = (const float*)d_in[9];
    const float* b_z  = (const float*)d_in[10];
    const float* W_m  = (const float*)d_in[11];
    const float* b_m  = (const float*)d_in[12];
    float* out = (float*)d_out;

    void *pA0h, *pA0l, *phh, *phl, *puh, *pul, *ph, *pwin, *pw1, *pw2, *pwz;
    cudaGetSymbolAddress(&pA0h, g_A0h);
    cudaGetSymbolAddress(&pA0l, g_A0l);
    cudaGetSymbolAddress(&phh, g_hh);
    cudaGetSymbolAddress(&phl, g_hl);
    cudaGetSymbolAddress(&puh, g_uh);
    cudaGetSymbolAddress(&pul, g_ul);
    cudaGetSymbolAddress(&ph, g_h);
    cudaGetSymbolAddress(&pwin, g_wq_in);
    cudaGetSymbolAddress(&pw1, g_wq1);
    cudaGetSymbolAddress(&pw2, g_wq2);
    cudaGetSymbolAddress(&pwz, g_wqz);
    void* pwm; cudaGetSymbolAddress(&pwm, g_wqm);

    __nv_bfloat16* wq_in = (__nv_bfloat16*)pwin;
    __nv_bfloat16* wq1   = (__nv_bfloat16*)pw1;
    __nv_bfloat16* wq2   = (__nv_bfloat16*)pw2;
    __nv_bfloat16* wqz   = (__nv_bfloat16*)pwz;
    __nv_bfloat16* wqm   = (__nv_bfloat16*)pwm;

    // 1) per-tensor scales (deterministic two-pass fp64 mean)
    k_abssum<<<NPART, 256>>>(W_in, (long)DIMX * KIN, 0);
    k_abssum<<<NPART, 256>>>(W1, (long)HIDX * DIMX, 1);
    k_abssum<<<NPART, 256>>>(W1 + (size_t)HIDX * DIMX, (long)HIDX * DIMX, 2);
    k_abssum<<<NPART, 256>>>(W2, (long)DIMX * HIDX, 3);
    k_abssum<<<NPART, 256>>>(W2 + (size_t)DIMX * HIDX, (long)DIMX * HIDX, 4);
    k_abssum<<<NPART, 256>>>(W_z, (long)DIMX * DIMX, 5);
    k_abssum<<<NPART, 256>>>(W_m, (long)DIMX, 6);
    k_finalize<<<1, 32>>>();

    // 2) ternary-quantize weights (stored as exact bf16 {-1,0,1}; scale in epilogue)
    k_quant<<<2048, 256>>>(W_in, wq_in, (long)DIMX * KIN, 0);
    k_quant<<<2048, 256>>>(W1, wq1, (long)HIDX * DIMX, 1);
    k_quant<<<2048, 256>>>(W1 + (size_t)HIDX * DIMX, wq1 + (size_t)HIDX * DIMX,
                           (long)HIDX * DIMX, 2);
    k_quant<<<2048, 256>>>(W2, wq2, (long)DIMX * HIDX, 3);
    k_quant<<<2048, 256>>>(W2 + (size_t)DIMX * HIDX, wq2 + (size_t)DIMX * HIDX,
                           (long)DIMX * HIDX, 4);
    k_quant<<<2048, 256>>>(W_z, wqz, (long)DIMX * DIMX, 5);
    k_quant<<<8, 256>>>(W_m, wqm, (long)DIMX, 6);

    // 3) concat + split inputs
    k_build_a0<<<8192, 256>>>(x, y, sp);

    dim3 gD(DIMX / 128, NROWS / 128);   // (8, 162)
    dim3 gH(HIDX / 128, NROWS / 128);   // (32, 162)

    // 4) h = A0 @ Wq_in^T + b_in
    k_gemm<EPI_H><<<gD, 256>>>((__nv_bfloat16*)pA0h, (__nv_bfloat16*)pA0l, wq_in, KIN,
                               b_in, 0, DIMX, (float*)ph,
                               (__nv_bfloat16*)phh, (__nv_bfloat16*)phl, nullptr);
    // 5) residual BitMLP blocks
    for (int l = 0; l < 2; l++) {
        k_gemm<EPI_GELU><<<gH, 256>>>(
            (__nv_bfloat16*)phh, (__nv_bfloat16*)phl, wq1 + (size_t)l * HIDX * DIMX,
            DIMX, b1 + (size_t)l * HIDX, 1 + l, HIDX, nullptr,
            (__nv_bfloat16*)puh, (__nv_bfloat16*)pul, nullptr);
        k_gemm<EPI_RES><<<gD, 256>>>(
            (__nv_bfloat16*)puh, (__nv_bfloat16*)pul, wq2 + (size_t)l * DIMX * HIDX,
            HIDX, b2 + (size_t)l * DIMX, 3 + l, DIMX, (float*)ph,
            (__nv_bfloat16*)phh, (__nv_bfloat16*)phl, nullptr);
    }
    // 6) z = h @ Wq_z^T + b_z   (written straight to d_out)
    k_gemm<EPI_Z><<<gD, 256>>>((__nv_bfloat16*)phh, (__nv_bfloat16*)phl, wqz, DIMX,
                               b_z, 5, DIMX, nullptr, nullptr, nullptr, out);
    // 7) focus_mask = sigmoid(h @ Wq_m^T + b_m)
    k_focus<<<NROWS / 8, 256>>>((const float*)ph, b_m, out + (size_t)NROWS * DIMX);
}